// round 1
// baseline (speedup 1.0000x reference)
#include <cuda_runtime.h>
#include <math.h>
#include <stdint.h>

// ---------------- Problem constants ----------------
#define NN    30000
#define EE    480000
#define ETOT  (EE + NN)      // edges + self loops
#define FIN   4096
#define D1    512            // HEADS*HID
#define H1    4
#define C1    128
#define CLS   6
#define SLOPE 0.2f

// ---------------- Device scratch (no allocations allowed) ----------------
__device__ float g_h1[(size_t)NN * D1];     // x @ W1
__device__ float g_out1[(size_t)NN * D1];   // layer-1 output after bias+ELU (input to layer 2)
__device__ float g_asrc1[NN * H1];
__device__ float g_adst1[NN * H1];
__device__ float g_h2[NN * CLS];            // elu_out @ W2
__device__ float g_as2[NN];
__device__ float g_ad2[NN];
__device__ int   g_deg[NN];
__device__ int   g_off[NN + 1];
__device__ int   g_cur[NN];
__device__ int   g_srcs[ETOT];              // CSR-by-dst: source node per slot

__device__ __forceinline__ float lrelu(float v) { return v > 0.0f ? v : SLOPE * v; }

// ---------------- GEMM1: g_h1 = x @ W1  (fp32 SIMT tiled) ----------------
// A: [NN, FIN] row-major, B: [FIN, D1] row-major, C: [NN, D1]
#define BM 128
#define BN 128
#define BK 8
#define TM 8
#define TN 8

__global__ __launch_bounds__(256) void sgemm1_kernel(const float* __restrict__ A,
                                                     const float* __restrict__ B) {
    __shared__ __align__(16) float As[BK][BM];
    __shared__ __align__(16) float Bs[BK][BN];

    const int block_row = blockIdx.y * BM;
    const int block_col = blockIdx.x * BN;
    const int tid = threadIdx.x;

    const int tr = (tid / 16) * TM;   // 0..120
    const int tc = (tid % 16) * TN;   // 0..120

    // A tile load: 128 rows x 8 k — float4 per thread
    const int a_row = tid >> 1;            // 0..127
    const int a_col = (tid & 1) * 4;       // 0 or 4
    // B tile load: 8 k x 128 cols — float4 per thread
    const int b_row = tid >> 5;            // 0..7
    const int b_col = (tid & 31) * 4;      // 0..124

    float acc[TM][TN];
#pragma unroll
    for (int i = 0; i < TM; i++)
#pragma unroll
        for (int j = 0; j < TN; j++) acc[i][j] = 0.0f;

    const int grow_a = block_row + a_row;
    const bool a_ok = (grow_a < NN);
    const float* aptr = A + (size_t)grow_a * FIN + a_col;
    const float* bptr = B + (size_t)b_row * D1 + block_col + b_col;

    for (int k0 = 0; k0 < FIN; k0 += BK) {
        float4 av = make_float4(0.f, 0.f, 0.f, 0.f);
        if (a_ok) av = *(const float4*)(aptr + k0);
        As[a_col + 0][a_row] = av.x;
        As[a_col + 1][a_row] = av.y;
        As[a_col + 2][a_row] = av.z;
        As[a_col + 3][a_row] = av.w;

        float4 bv = *(const float4*)(bptr + (size_t)k0 * D1);
        *(float4*)&Bs[b_row][b_col] = bv;
        __syncthreads();

#pragma unroll
        for (int kk = 0; kk < BK; kk++) {
            float4 a0 = *(const float4*)&As[kk][tr];
            float4 a1 = *(const float4*)&As[kk][tr + 4];
            float4 b0 = *(const float4*)&Bs[kk][tc];
            float4 b1 = *(const float4*)&Bs[kk][tc + 4];
            float ar[TM] = {a0.x, a0.y, a0.z, a0.w, a1.x, a1.y, a1.z, a1.w};
            float br[TN] = {b0.x, b0.y, b0.z, b0.w, b1.x, b1.y, b1.z, b1.w};
#pragma unroll
            for (int i = 0; i < TM; i++)
#pragma unroll
                for (int j = 0; j < TN; j++) acc[i][j] = fmaf(ar[i], br[j], acc[i][j]);
        }
        __syncthreads();
    }

#pragma unroll
    for (int i = 0; i < TM; i++) {
        int grow = block_row + tr + i;
        if (grow >= NN) break;
        float* crow = g_h1 + (size_t)grow * D1 + block_col + tc;
#pragma unroll
        for (int j = 0; j < TN; j += 4)
            *(float4*)(crow + j) = make_float4(acc[i][j], acc[i][j + 1], acc[i][j + 2], acc[i][j + 3]);
    }
}

// ---------------- CSR build ----------------
__global__ void zero_deg_kernel() {
    int i = blockIdx.x * blockDim.x + threadIdx.x;
    if (i < NN) g_deg[i] = 0;
}

__global__ void count_kernel(const int* __restrict__ ei) {
    int e = blockIdx.x * blockDim.x + threadIdx.x;
    if (e >= ETOT) return;
    int dst = (e < EE) ? ei[EE + e] : (e - EE);
    atomicAdd(&g_deg[dst], 1);
}

__global__ __launch_bounds__(1024) void scan_kernel() {
    __shared__ int part[1024];
    const int t = threadIdx.x;
    const int CH = (NN + 1023) / 1024;   // 30
    const int base = t * CH;
    int s = 0;
    for (int i = 0; i < CH; i++) {
        int idx = base + i;
        if (idx < NN) s += g_deg[idx];
    }
    part[t] = s;
    __syncthreads();
    for (int o = 1; o < 1024; o <<= 1) {
        int v = (t >= o) ? part[t - o] : 0;
        __syncthreads();
        part[t] += v;
        __syncthreads();
    }
    int run = part[t] - s;   // exclusive prefix for this chunk
    for (int i = 0; i < CH; i++) {
        int idx = base + i;
        if (idx < NN) {
            g_off[idx] = run;
            g_cur[idx] = run;
            run += g_deg[idx];
        }
    }
    if (t == 1023) g_off[NN] = part[1023];
}

__global__ void scatter_kernel(const int* __restrict__ ei) {
    int e = blockIdx.x * blockDim.x + threadIdx.x;
    if (e >= ETOT) return;
    int src, dst;
    if (e < EE) { src = ei[e]; dst = ei[EE + e]; }
    else        { src = e - EE; dst = e - EE; }
    int pos = atomicAdd(&g_cur[dst], 1);
    g_srcs[pos] = src;
}

// ---------------- Layer 1 alphas: warp per node ----------------
__global__ void alpha1_kernel(const float* __restrict__ a_s, const float* __restrict__ a_d) {
    int warp = blockIdx.x * 8 + (threadIdx.x >> 5);
    int lane = threadIdx.x & 31;
    if (warp >= NN) return;
    const float* row = g_h1 + (size_t)warp * D1;
#pragma unroll
    for (int h = 0; h < H1; h++) {
        float ss = 0.f, sd = 0.f;
#pragma unroll
        for (int k = 0; k < 4; k++) {
            int c = h * C1 + lane + 32 * k;
            float v = row[c];
            ss = fmaf(v, a_s[c], ss);
            sd = fmaf(v, a_d[c], sd);
        }
#pragma unroll
        for (int o = 16; o; o >>= 1) {
            ss += __shfl_xor_sync(0xffffffffu, ss, o);
            sd += __shfl_xor_sync(0xffffffffu, sd, o);
        }
        if (lane == 0) {
            g_asrc1[warp * H1 + h] = ss;
            g_adst1[warp * H1 + h] = sd;
        }
    }
}

// ---------------- Layer 1 fused softmax + aggregate + bias + ELU ----------------
// One 128-thread block per destination node. Atomic-free via CSR.
__global__ __launch_bounds__(128) void agg1_kernel(const float* __restrict__ b1) {
    const int n = blockIdx.x;
    const int t = threadIdx.x;
    const int s0 = g_off[n];
    const int deg = g_off[n + 1] - s0;

    __shared__ float adsts[H1];
    __shared__ float sm[H1];       // per-head max
    __shared__ float sinv[H1];     // per-head 1/denom
    __shared__ float red[128 * H1];
    __shared__ int   ssrc[128];
    __shared__ float scoef[128 * H1];

    if (t < H1) adsts[t] = g_adst1[n * H1 + t];
    __syncthreads();

    // phase 1: max logit per head
    float lm[H1] = {-INFINITY, -INFINITY, -INFINITY, -INFINITY};
    for (int i = t; i < deg; i += 128) {
        int s = g_srcs[s0 + i];
#pragma unroll
        for (int h = 0; h < H1; h++) {
            float l = lrelu(g_asrc1[s * H1 + h] + adsts[h]);
            lm[h] = fmaxf(lm[h], l);
        }
    }
#pragma unroll
    for (int h = 0; h < H1; h++) red[t * H1 + h] = lm[h];
    __syncthreads();
    if (t < H1) {
        float m = -INFINITY;
        for (int i = 0; i < 128; i++) m = fmaxf(m, red[i * H1 + t]);
        sm[t] = m;
    }
    __syncthreads();

    // phase 2: denominator per head
    float ls[H1] = {0.f, 0.f, 0.f, 0.f};
    for (int i = t; i < deg; i += 128) {
        int s = g_srcs[s0 + i];
#pragma unroll
        for (int h = 0; h < H1; h++) {
            float l = lrelu(g_asrc1[s * H1 + h] + adsts[h]);
            ls[h] += expf(l - sm[h]);
        }
    }
#pragma unroll
    for (int h = 0; h < H1; h++) red[t * H1 + h] = ls[h];
    __syncthreads();
    if (t < H1) {
        float s = 0.f;
        for (int i = 0; i < 128; i++) s += red[i * H1 + t];
        sinv[t] = 1.0f / s;
    }
    __syncthreads();

    // phase 3: chunked aggregation. Thread t owns channel t of each head.
    float acc0 = 0.f, acc1 = 0.f, acc2 = 0.f, acc3 = 0.f;
    for (int base = 0; base < deg; base += 128) {
        int cnt = min(128, deg - base);
        if (t < cnt) {
            int s = g_srcs[s0 + base + t];
            ssrc[t] = s;
#pragma unroll
            for (int h = 0; h < H1; h++) {
                float l = lrelu(g_asrc1[s * H1 + h] + adsts[h]);
                scoef[t * H1 + h] = expf(l - sm[h]) * sinv[h];
            }
        }
        __syncthreads();
        for (int i = 0; i < cnt; i++) {
            const float* hp = g_h1 + (size_t)ssrc[i] * D1 + t;
            float c0 = scoef[i * H1 + 0];
            float c1 = scoef[i * H1 + 1];
            float c2 = scoef[i * H1 + 2];
            float c3 = scoef[i * H1 + 3];
            acc0 = fmaf(c0, hp[0],       acc0);
            acc1 = fmaf(c1, hp[C1],      acc1);
            acc2 = fmaf(c2, hp[2 * C1],  acc2);
            acc3 = fmaf(c3, hp[3 * C1],  acc3);
        }
        __syncthreads();
    }

    // bias + ELU, write
    float* orow = g_out1 + (size_t)n * D1;
    float v;
    v = acc0 + b1[t];           orow[t]          = v > 0.f ? v : expm1f(v);
    v = acc1 + b1[C1 + t];      orow[C1 + t]     = v > 0.f ? v : expm1f(v);
    v = acc2 + b1[2 * C1 + t];  orow[2 * C1 + t] = v > 0.f ? v : expm1f(v);
    v = acc3 + b1[3 * C1 + t];  orow[3 * C1 + t] = v > 0.f ? v : expm1f(v);
}

// ---------------- Layer 2 small GEMM: g_h2 = g_out1 @ W2 ----------------
__global__ __launch_bounds__(256) void gemm2_kernel(const float* __restrict__ W2) {
    __shared__ float w[D1 * CLS];
    int t = threadIdx.x;
    for (int i = t; i < D1 * CLS; i += 256) w[i] = W2[i];
    __syncthreads();
    int warp = blockIdx.x * 8 + (t >> 5);
    int lane = t & 31;
    if (warp >= NN) return;
    const float* row = g_out1 + (size_t)warp * D1;
    float acc[CLS] = {0.f, 0.f, 0.f, 0.f, 0.f, 0.f};
    for (int k = lane; k < D1; k += 32) {
        float v = row[k];
        const float* wr = &w[k * CLS];
#pragma unroll
        for (int c = 0; c < CLS; c++) acc[c] = fmaf(v, wr[c], acc[c]);
    }
#pragma unroll
    for (int o = 16; o; o >>= 1)
#pragma unroll
        for (int c = 0; c < CLS; c++) acc[c] += __shfl_xor_sync(0xffffffffu, acc[c], o);
    if (lane == 0) {
#pragma unroll
        for (int c = 0; c < CLS; c++) g_h2[warp * CLS + c] = acc[c];
    }
}

__global__ void alpha2_kernel(const float* __restrict__ a_s, const float* __restrict__ a_d) {
    int n = blockIdx.x * blockDim.x + threadIdx.x;
    if (n >= NN) return;
    float s = 0.f, d = 0.f;
#pragma unroll
    for (int c = 0; c < CLS; c++) {
        float v = g_h2[n * CLS + c];
        s = fmaf(v, a_s[c], s);
        d = fmaf(v, a_d[c], d);
    }
    g_as2[n] = s;
    g_ad2[n] = d;
}

// ---------------- Layer 2 aggregation: warp per destination ----------------
__global__ __launch_bounds__(128) void agg2_kernel(const float* __restrict__ b2,
                                                   float* __restrict__ out) {
    int n = blockIdx.x * 4 + (threadIdx.x >> 5);
    int lane = threadIdx.x & 31;
    if (n >= NN) return;
    int s0 = g_off[n];
    int deg = g_off[n + 1] - s0;
    float ad = g_ad2[n];

    float lmax = -INFINITY;
    for (int i = lane; i < deg; i += 32) {
        int s = g_srcs[s0 + i];
        lmax = fmaxf(lmax, lrelu(g_as2[s] + ad));
    }
#pragma unroll
    for (int o = 16; o; o >>= 1) lmax = fmaxf(lmax, __shfl_xor_sync(0xffffffffu, lmax, o));

    float lsum = 0.f;
    for (int i = lane; i < deg; i += 32) {
        int s = g_srcs[s0 + i];
        lsum += expf(lrelu(g_as2[s] + ad) - lmax);
    }
#pragma unroll
    for (int o = 16; o; o >>= 1) lsum += __shfl_xor_sync(0xffffffffu, lsum, o);
    float inv = 1.0f / lsum;

    float acc[CLS] = {0.f, 0.f, 0.f, 0.f, 0.f, 0.f};
    for (int i = lane; i < deg; i += 32) {
        int s = g_srcs[s0 + i];
        float coef = expf(lrelu(g_as2[s] + ad) - lmax) * inv;
        const float* hp = g_h2 + s * CLS;
#pragma unroll
        for (int c = 0; c < CLS; c++) acc[c] = fmaf(coef, hp[c], acc[c]);
    }
#pragma unroll
    for (int o = 16; o; o >>= 1)
#pragma unroll
        for (int c = 0; c < CLS; c++) acc[c] += __shfl_xor_sync(0xffffffffu, acc[c], o);

    if (lane == 0) {
#pragma unroll
        for (int c = 0; c < CLS; c++) out[n * CLS + c] = acc[c] + b2[c];
    }
}

// ---------------- Launch ----------------
extern "C" void kernel_launch(void* const* d_in, const int* in_sizes, int n_in,
                              void* d_out, int out_size) {
    const float* x   = (const float*)d_in[0];
    const int*   ei  = (const int*)  d_in[1];
    const float* W1  = (const float*)d_in[2];
    const float* as1 = (const float*)d_in[3];
    const float* ad1 = (const float*)d_in[4];
    const float* b1  = (const float*)d_in[5];
    const float* W2  = (const float*)d_in[6];
    const float* as2 = (const float*)d_in[7];
    const float* ad2 = (const float*)d_in[8];
    const float* b2  = (const float*)d_in[9];
    float* out = (float*)d_out;

    // CSR build (reused by both layers)
    zero_deg_kernel<<<(NN + 255) / 256, 256>>>();
    count_kernel<<<(ETOT + 255) / 256, 256>>>(ei);
    scan_kernel<<<1, 1024>>>();
    scatter_kernel<<<(ETOT + 255) / 256, 256>>>(ei);

    // Layer 1
    sgemm1_kernel<<<dim3(D1 / BN, (NN + BM - 1) / BM), 256>>>(x, W1);
    alpha1_kernel<<<(NN + 7) / 8, 256>>>(as1, ad1);
    agg1_kernel<<<NN, 128>>>(b1);

    // Layer 2
    gemm2_kernel<<<(NN + 7) / 8, 256>>>(W2);
    alpha2_kernel<<<(NN + 255) / 256, 256>>>(as2, ad2);
    agg2_kernel<<<(NN + 3) / 4, 128>>>(b2, out);
}

// round 3
// speedup vs baseline: 2.2249x; 2.2249x over previous
#include <cuda_runtime.h>
#include <cuda_bf16.h>
#include <math.h>
#include <stdint.h>

// ---------------- Problem constants ----------------
#define NN    30000
#define EE    480000
#define ETOT  (EE + NN)
#define FIN   4096
#define D1    512
#define H1    4
#define C1    128
#define CLS   6
#define SLOPE 0.2f

// ---------------- Device scratch ----------------
__device__ float g_h1[(size_t)NN * D1];
__device__ float g_out1[(size_t)NN * D1];
__device__ float g_asrc1[NN * H1];
__device__ float g_adst1[NN * H1];
__device__ float g_h2[NN * CLS];
__device__ float g_as2[NN];
__device__ float g_ad2[NN];
__device__ int   g_deg[NN];
__device__ int   g_off[NN + 1];
__device__ int   g_cur[NN];
__device__ int   g_srcs[ETOT];

// bf16 split operands
__device__ __nv_bfloat16 g_xhi[(size_t)NN * FIN];
__device__ __nv_bfloat16 g_xlo[(size_t)NN * FIN];
__device__ __nv_bfloat16 g_w1thi[(size_t)D1 * FIN];   // transposed: [N=512][K=4096]
__device__ __nv_bfloat16 g_w1tlo[(size_t)D1 * FIN];

__device__ __forceinline__ float lrelu(float v) { return v > 0.0f ? v : SLOPE * v; }

// ==================== helpers ====================
__device__ __forceinline__ uint32_t smem_u32(const void* p) {
    uint32_t a;
    asm("{ .reg .u64 t; cvta.to.shared.u64 t, %1; cvt.u32.u64 %0, t; }" : "=r"(a) : "l"(p));
    return a;
}

__device__ __forceinline__ void cpa16(uint32_t dst, const void* src, uint32_t bytes) {
    asm volatile("cp.async.cg.shared.global [%0], [%1], 16, %2;\n"
                 :: "r"(dst), "l"(src), "r"(bytes) : "memory");
}

__device__ __forceinline__ void ldm_x4(uint32_t addr, uint32_t& r0, uint32_t& r1,
                                       uint32_t& r2, uint32_t& r3) {
    asm volatile("ldmatrix.sync.aligned.m8n8.x4.shared.b16 {%0,%1,%2,%3}, [%4];"
                 : "=r"(r0), "=r"(r1), "=r"(r2), "=r"(r3) : "r"(addr));
}

__device__ __forceinline__ void mma_bf16(float& d0, float& d1, float& d2, float& d3,
                                         uint32_t a0, uint32_t a1, uint32_t a2, uint32_t a3,
                                         uint32_t b0, uint32_t b1) {
    asm volatile("mma.sync.aligned.m16n8k16.row.col.f32.bf16.bf16.f32 "
                 "{%0,%1,%2,%3}, {%4,%5,%6,%7}, {%8,%9}, {%0,%1,%2,%3};"
                 : "+f"(d0), "+f"(d1), "+f"(d2), "+f"(d3)
                 : "r"(a0), "r"(a1), "r"(a2), "r"(a3), "r"(b0), "r"(b1));
}

// ==================== bf16-split conversion ====================
__global__ __launch_bounds__(256) void convx_kernel(const float* __restrict__ x) {
    size_t i = ((size_t)blockIdx.x * 256 + threadIdx.x) * 4;
    if (i >= (size_t)NN * FIN) return;
    float4 v = *(const float4*)(x + i);
    __nv_bfloat16 h0 = __float2bfloat16(v.x);
    __nv_bfloat16 h1 = __float2bfloat16(v.y);
    __nv_bfloat16 h2 = __float2bfloat16(v.z);
    __nv_bfloat16 h3 = __float2bfloat16(v.w);
    __nv_bfloat16 l0 = __float2bfloat16(v.x - __bfloat162float(h0));
    __nv_bfloat16 l1 = __float2bfloat16(v.y - __bfloat162float(h1));
    __nv_bfloat16 l2 = __float2bfloat16(v.z - __bfloat162float(h2));
    __nv_bfloat16 l3 = __float2bfloat16(v.w - __bfloat162float(h3));
    __nv_bfloat162 hv0 = __halves2bfloat162(h0, h1);
    __nv_bfloat162 hv1 = __halves2bfloat162(h2, h3);
    __nv_bfloat162 lv0 = __halves2bfloat162(l0, l1);
    __nv_bfloat162 lv1 = __halves2bfloat162(l2, l3);
    uint2 hv, lv;
    hv.x = *(uint32_t*)&hv0; hv.y = *(uint32_t*)&hv1;
    lv.x = *(uint32_t*)&lv0; lv.y = *(uint32_t*)&lv1;
    *(uint2*)(g_xhi + i) = hv;
    *(uint2*)(g_xlo + i) = lv;
}

__global__ __launch_bounds__(256) void convw1_kernel(const float* __restrict__ W1) {
    int idx = blockIdx.x * 256 + threadIdx.x;   // over FIN * D1
    if (idx >= FIN * D1) return;
    int k = idx >> 9;
    int n = idx & 511;
    float v = W1[idx];
    __nv_bfloat16 h = __float2bfloat16(v);
    __nv_bfloat16 l = __float2bfloat16(v - __bfloat162float(h));
    g_w1thi[(size_t)n * FIN + k] = h;
    g_w1tlo[(size_t)n * FIN + k] = l;
}

// ==================== GEMM1: mma.sync bf16-split ====================
// C[128 x 128] per CTA, BK=32, 3-stage cp.async pipeline, 8 warps (64x32 warp tile)
#define BK       32
#define CHUNKS   (FIN / BK)     // 128
#define SROW     40             // padded row stride in bf16 elems (80 bytes)
#define TILE_B   (128 * SROW * 2)   // 10240 bytes per tile
#define OFF_AHI  0
#define OFF_ALO  (TILE_B)
#define OFF_BHI  (2 * TILE_B)
#define OFF_BLO  (3 * TILE_B)
#define STAGE_B  (4 * TILE_B)       // 40960
#define NSTAGE   3
#define SMEM_SZ  (NSTAGE * STAGE_B) // 122880

__global__ __launch_bounds__(256) void mma1_kernel() {
    extern __shared__ __align__(16) char dsm[];
    const uint32_t sb = smem_u32(dsm);

    const int tid = threadIdx.x;
    const int wid = tid >> 5;
    const int lane = tid & 31;
    const int warp_m = wid >> 2;    // 0..1
    const int warp_n = wid & 3;     // 0..3
    const int block_row = blockIdx.y * 128;
    const int nbase = blockIdx.x * 128;

    // per-thread cp.async source/dest decomposition: i in [0,512): r=i>>2, q=i&3
    // dst byte = r*80 + q*16 ; src elem = row_global*FIN + c*32 + q*8
    const int lr = tid >> 1;          // not used directly; loads via loop below

    auto ld_chunk = [&](int c, int s) {
        const uint32_t stg = sb + s * STAGE_B;
        const int kbase = c * BK;
#pragma unroll
        for (int i = tid; i < 512; i += 256) {
            int r = i >> 2, q = i & 3;
            uint32_t dso = (uint32_t)(r * 80 + q * 16);
            int grow = block_row + r;
            uint32_t ok = (grow < NN) ? 16u : 0u;
            size_t se = (size_t)grow * FIN + kbase + q * 8;
            cpa16(stg + OFF_AHI + dso, g_xhi + se, ok);
            cpa16(stg + OFF_ALO + dso, g_xlo + se, ok);
        }
#pragma unroll
        for (int i = tid; i < 512; i += 256) {
            int r = i >> 2, q = i & 3;
            uint32_t dso = (uint32_t)(r * 80 + q * 16);
            size_t se = (size_t)(nbase + r) * FIN + kbase + q * 8;
            cpa16(stg + OFF_BHI + dso, g_w1thi + se, 16u);
            cpa16(stg + OFF_BLO + dso, g_w1tlo + se, 16u);
        }
    };

    // ldmatrix per-thread base offsets (within a tile)
    // A: row = warp_m*64 + i*16 + (lane&15), byte col = (lane>>4)*16 + kk*32
    const uint32_t a_off = (uint32_t)((warp_m * 64 + (lane & 15)) * 80 + (lane >> 4) * 16);
    // B: row = warp_n*32 + j2*16 + (lane&7) + ((lane>>4)<<3), byte col = ((lane>>3)&1)*16 + kk*32
    const uint32_t b_off = (uint32_t)((warp_n * 32 + (lane & 7) + ((lane >> 4) << 3)) * 80 +
                                      ((lane >> 3) & 1) * 16);

    float acc[4][4][4];
#pragma unroll
    for (int i = 0; i < 4; i++)
#pragma unroll
        for (int j = 0; j < 4; j++)
#pragma unroll
            for (int q = 0; q < 4; q++) acc[i][j][q] = 0.0f;

    // prologue: stages 0,1
    ld_chunk(0, 0);
    asm volatile("cp.async.commit_group;\n" ::: "memory");
    ld_chunk(1, 1);
    asm volatile("cp.async.commit_group;\n" ::: "memory");

    for (int c = 0; c < CHUNKS; c++) {
        const int s = c % NSTAGE;
        asm volatile("cp.async.wait_group 1;\n" ::: "memory");
        __syncthreads();

        const uint32_t stg = sb + s * STAGE_B;
        const uint32_t a_hi = stg + OFF_AHI + a_off;
        const uint32_t a_lo = stg + OFF_ALO + a_off;
        const uint32_t b_hi = stg + OFF_BHI + b_off;
        const uint32_t b_lo = stg + OFF_BLO + b_off;

#pragma unroll
        for (int kk = 0; kk < 2; kk++) {
            uint32_t ahi[4][4], alo[4][4], bhi[4][2], blo[4][2];
#pragma unroll
            for (int i = 0; i < 4; i++) {
                uint32_t ao = (uint32_t)(i * 16 * 80 + kk * 32);
                ldm_x4(a_hi + ao, ahi[i][0], ahi[i][1], ahi[i][2], ahi[i][3]);
                ldm_x4(a_lo + ao, alo[i][0], alo[i][1], alo[i][2], alo[i][3]);
            }
#pragma unroll
            for (int j2 = 0; j2 < 2; j2++) {
                uint32_t bo = (uint32_t)(j2 * 16 * 80 + kk * 32);
                ldm_x4(b_hi + bo, bhi[2 * j2][0], bhi[2 * j2][1], bhi[2 * j2 + 1][0], bhi[2 * j2 + 1][1]);
                ldm_x4(b_lo + bo, blo[2 * j2][0], blo[2 * j2][1], blo[2 * j2 + 1][0], blo[2 * j2 + 1][1]);
            }
#pragma unroll
            for (int i = 0; i < 4; i++)
#pragma unroll
                for (int j = 0; j < 4; j++) {
                    float* d = acc[i][j];
                    mma_bf16(d[0], d[1], d[2], d[3],
                             ahi[i][0], ahi[i][1], ahi[i][2], ahi[i][3],
                             bhi[j][0], bhi[j][1]);
                    mma_bf16(d[0], d[1], d[2], d[3],
                             ahi[i][0], ahi[i][1], ahi[i][2], ahi[i][3],
                             blo[j][0], blo[j][1]);
                    mma_bf16(d[0], d[1], d[2], d[3],
                             alo[i][0], alo[i][1], alo[i][2], alo[i][3],
                             bhi[j][0], bhi[j][1]);
                }
        }
        __syncthreads();

        if (c + 2 < CHUNKS) ld_chunk(c + 2, (c + 2) % NSTAGE);
        asm volatile("cp.async.commit_group;\n" ::: "memory");
    }

    // epilogue
#pragma unroll
    for (int i = 0; i < 4; i++) {
        int row0 = block_row + warp_m * 64 + i * 16 + (lane >> 2);
#pragma unroll
        for (int j = 0; j < 4; j++) {
            int col = nbase + warp_n * 32 + j * 8 + (lane & 3) * 2;
            if (row0 < NN)
                *(float2*)(g_h1 + (size_t)row0 * D1 + col) = make_float2(acc[i][j][0], acc[i][j][1]);
            if (row0 + 8 < NN)
                *(float2*)(g_h1 + (size_t)(row0 + 8) * D1 + col) = make_float2(acc[i][j][2], acc[i][j][3]);
        }
    }
}

// ==================== CSR build ====================
__global__ void zero_deg_kernel() {
    int i = blockIdx.x * blockDim.x + threadIdx.x;
    if (i < NN) g_deg[i] = 0;
}

__global__ void count_kernel(const int* __restrict__ ei) {
    int e = blockIdx.x * blockDim.x + threadIdx.x;
    if (e >= ETOT) return;
    int dst = (e < EE) ? ei[EE + e] : (e - EE);
    atomicAdd(&g_deg[dst], 1);
}

__global__ __launch_bounds__(1024) void scan_kernel() {
    __shared__ int part[1024];
    const int t = threadIdx.x;
    const int CH = (NN + 1023) / 1024;
    const int base = t * CH;
    int s = 0;
    for (int i = 0; i < CH; i++) {
        int idx = base + i;
        if (idx < NN) s += g_deg[idx];
    }
    part[t] = s;
    __syncthreads();
    for (int o = 1; o < 1024; o <<= 1) {
        int v = (t >= o) ? part[t - o] : 0;
        __syncthreads();
        part[t] += v;
        __syncthreads();
    }
    int run = part[t] - s;
    for (int i = 0; i < CH; i++) {
        int idx = base + i;
        if (idx < NN) {
            g_off[idx] = run;
            g_cur[idx] = run;
            run += g_deg[idx];
        }
    }
    if (t == 1023) g_off[NN] = part[1023];
}

__global__ void scatter_kernel(const int* __restrict__ ei) {
    int e = blockIdx.x * blockDim.x + threadIdx.x;
    if (e >= ETOT) return;
    int src, dst;
    if (e < EE) { src = ei[e]; dst = ei[EE + e]; }
    else        { src = e - EE; dst = e - EE; }
    int pos = atomicAdd(&g_cur[dst], 1);
    g_srcs[pos] = src;
}

// ==================== Layer 1 alphas ====================
__global__ void alpha1_kernel(const float* __restrict__ a_s, const float* __restrict__ a_d) {
    int warp = blockIdx.x * 8 + (threadIdx.x >> 5);
    int lane = threadIdx.x & 31;
    if (warp >= NN) return;
    const float* row = g_h1 + (size_t)warp * D1;
#pragma unroll
    for (int h = 0; h < H1; h++) {
        float ss = 0.f, sd = 0.f;
#pragma unroll
        for (int k = 0; k < 4; k++) {
            int c = h * C1 + lane + 32 * k;
            float v = row[c];
            ss = fmaf(v, a_s[c], ss);
            sd = fmaf(v, a_d[c], sd);
        }
#pragma unroll
        for (int o = 16; o; o >>= 1) {
            ss += __shfl_xor_sync(0xffffffffu, ss, o);
            sd += __shfl_xor_sync(0xffffffffu, sd, o);
        }
        if (lane == 0) {
            g_asrc1[warp * H1 + h] = ss;
            g_adst1[warp * H1 + h] = sd;
        }
    }
}

// ==================== Layer 1 softmax + aggregate + ELU ====================
__global__ __launch_bounds__(128) void agg1_kernel(const float* __restrict__ b1) {
    const int n = blockIdx.x;
    const int t = threadIdx.x;
    const int s0 = g_off[n];
    const int deg = g_off[n + 1] - s0;

    __shared__ float adsts[H1];
    __shared__ float sm[H1];
    __shared__ float sinv[H1];
    __shared__ float red[128 * H1];
    __shared__ int   ssrc[128];
    __shared__ float scoef[128 * H1];

    if (t < H1) adsts[t] = g_adst1[n * H1 + t];
    __syncthreads();

    float lm[H1] = {-INFINITY, -INFINITY, -INFINITY, -INFINITY};
    for (int i = t; i < deg; i += 128) {
        int s = g_srcs[s0 + i];
#pragma unroll
        for (int h = 0; h < H1; h++) {
            float l = lrelu(g_asrc1[s * H1 + h] + adsts[h]);
            lm[h] = fmaxf(lm[h], l);
        }
    }
#pragma unroll
    for (int h = 0; h < H1; h++) red[t * H1 + h] = lm[h];
    __syncthreads();
    if (t < H1) {
        float m = -INFINITY;
        for (int i = 0; i < 128; i++) m = fmaxf(m, red[i * H1 + t]);
        sm[t] = m;
    }
    __syncthreads();

    float ls[H1] = {0.f, 0.f, 0.f, 0.f};
    for (int i = t; i < deg; i += 128) {
        int s = g_srcs[s0 + i];
#pragma unroll
        for (int h = 0; h < H1; h++) {
            float l = lrelu(g_asrc1[s * H1 + h] + adsts[h]);
            ls[h] += expf(l - sm[h]);
        }
    }
#pragma unroll
    for (int h = 0; h < H1; h++) red[t * H1 + h] = ls[h];
    __syncthreads();
    if (t < H1) {
        float s = 0.f;
        for (int i = 0; i < 128; i++) s += red[i * H1 + t];
        sinv[t] = 1.0f / s;
    }
    __syncthreads();

    float acc0 = 0.f, acc1 = 0.f, acc2 = 0.f, acc3 = 0.f;
    for (int base = 0; base < deg; base += 128) {
        int cnt = min(128, deg - base);
        if (t < cnt) {
            int s = g_srcs[s0 + base + t];
            ssrc[t] = s;
#pragma unroll
            for (int h = 0; h < H1; h++) {
                float l = lrelu(g_asrc1[s * H1 + h] + adsts[h]);
                scoef[t * H1 + h] = expf(l - sm[h]) * sinv[h];
            }
        }
        __syncthreads();
        for (int i = 0; i < cnt; i++) {
            const float* hp = g_h1 + (size_t)ssrc[i] * D1 + t;
            float c0 = scoef[i * H1 + 0];
            float c1 = scoef[i * H1 + 1];
            float c2 = scoef[i * H1 + 2];
            float c3 = scoef[i * H1 + 3];
            acc0 = fmaf(c0, hp[0],      acc0);
            acc1 = fmaf(c1, hp[C1],     acc1);
            acc2 = fmaf(c2, hp[2 * C1], acc2);
            acc3 = fmaf(c3, hp[3 * C1], acc3);
        }
        __syncthreads();
    }

    float* orow = g_out1 + (size_t)n * D1;
    float v;
    v = acc0 + b1[t];           orow[t]          = v > 0.f ? v : expm1f(v);
    v = acc1 + b1[C1 + t];      orow[C1 + t]     = v > 0.f ? v : expm1f(v);
    v = acc2 + b1[2 * C1 + t];  orow[2 * C1 + t] = v > 0.f ? v : expm1f(v);
    v = acc3 + b1[3 * C1 + t];  orow[3 * C1 + t] = v > 0.f ? v : expm1f(v);
}

// ==================== Layer 2 ====================
__global__ __launch_bounds__(256) void gemm2_kernel(const float* __restrict__ W2) {
    __shared__ float w[D1 * CLS];
    int t = threadIdx.x;
    for (int i = t; i < D1 * CLS; i += 256) w[i] = W2[i];
    __syncthreads();
    int warp = blockIdx.x * 8 + (t >> 5);
    int lane = t & 31;
    if (warp >= NN) return;
    const float* row = g_out1 + (size_t)warp * D1;
    float acc[CLS] = {0.f, 0.f, 0.f, 0.f, 0.f, 0.f};
    for (int k = lane; k < D1; k += 32) {
        float v = row[k];
        const float* wr = &w[k * CLS];
#pragma unroll
        for (int c = 0; c < CLS; c++) acc[c] = fmaf(v, wr[c], acc[c]);
    }
#pragma unroll
    for (int o = 16; o; o >>= 1)
#pragma unroll
        for (int c = 0; c < CLS; c++) acc[c] += __shfl_xor_sync(0xffffffffu, acc[c], o);
    if (lane == 0) {
#pragma unroll
        for (int c = 0; c < CLS; c++) g_h2[warp * CLS + c] = acc[c];
    }
}

__global__ void alpha2_kernel(const float* __restrict__ a_s, const float* __restrict__ a_d) {
    int n = blockIdx.x * blockDim.x + threadIdx.x;
    if (n >= NN) return;
    float s = 0.f, d = 0.f;
#pragma unroll
    for (int c = 0; c < CLS; c++) {
        float v = g_h2[n * CLS + c];
        s = fmaf(v, a_s[c], s);
        d = fmaf(v, a_d[c], d);
    }
    g_as2[n] = s;
    g_ad2[n] = d;
}

__global__ __launch_bounds__(128) void agg2_kernel(const float* __restrict__ b2,
                                                   float* __restrict__ out) {
    int n = blockIdx.x * 4 + (threadIdx.x >> 5);
    int lane = threadIdx.x & 31;
    if (n >= NN) return;
    int s0 = g_off[n];
    int deg = g_off[n + 1] - s0;
    float ad = g_ad2[n];

    float lmax = -INFINITY;
    for (int i = lane; i < deg; i += 32) {
        int s = g_srcs[s0 + i];
        lmax = fmaxf(lmax, lrelu(g_as2[s] + ad));
    }
#pragma unroll
    for (int o = 16; o; o >>= 1) lmax = fmaxf(lmax, __shfl_xor_sync(0xffffffffu, lmax, o));

    float lsum = 0.f;
    for (int i = lane; i < deg; i += 32) {
        int s = g_srcs[s0 + i];
        lsum += expf(lrelu(g_as2[s] + ad) - lmax);
    }
#pragma unroll
    for (int o = 16; o; o >>= 1) lsum += __shfl_xor_sync(0xffffffffu, lsum, o);
    float inv = 1.0f / lsum;

    float acc[CLS] = {0.f, 0.f, 0.f, 0.f, 0.f, 0.f};
    for (int i = lane; i < deg; i += 32) {
        int s = g_srcs[s0 + i];
        float coef = expf(lrelu(g_as2[s] + ad) - lmax) * inv;
        const float* hp = g_h2 + s * CLS;
#pragma unroll
        for (int c = 0; c < CLS; c++) acc[c] = fmaf(coef, hp[c], acc[c]);
    }
#pragma unroll
    for (int o = 16; o; o >>= 1)
#pragma unroll
        for (int c = 0; c < CLS; c++) acc[c] += __shfl_xor_sync(0xffffffffu, acc[c], o);

    if (lane == 0) {
#pragma unroll
        for (int c = 0; c < CLS; c++) out[n * CLS + c] = acc[c] + b2[c];
    }
}

// ==================== Launch ====================
extern "C" void kernel_launch(void* const* d_in, const int* in_sizes, int n_in,
                              void* d_out, int out_size) {
    const float* x   = (const float*)d_in[0];
    const int*   ei  = (const int*)  d_in[1];
    const float* W1  = (const float*)d_in[2];
    const float* as1 = (const float*)d_in[3];
    const float* ad1 = (const float*)d_in[4];
    const float* b1  = (const float*)d_in[5];
    const float* W2  = (const float*)d_in[6];
    const float* as2 = (const float*)d_in[7];
    const float* ad2 = (const float*)d_in[8];
    const float* b2  = (const float*)d_in[9];
    float* out = (float*)d_out;

    static bool attr_set = false;
    if (!attr_set) {
        cudaFuncSetAttribute(mma1_kernel, cudaFuncAttributeMaxDynamicSharedMemorySize, SMEM_SZ);
        attr_set = true;
    }

    // CSR build
    zero_deg_kernel<<<(NN + 255) / 256, 256>>>();
    count_kernel<<<(ETOT + 255) / 256, 256>>>(ei);
    scan_kernel<<<1, 1024>>>();
    scatter_kernel<<<(ETOT + 255) / 256, 256>>>(ei);

    // bf16 split conversion
    convx_kernel<<<(int)(((size_t)NN * FIN / 4 + 255) / 256), 256>>>(x);
    convw1_kernel<<<(FIN * D1 + 255) / 256, 256>>>(W1);

    // Layer 1: mma.sync GEMM + attention
    mma1_kernel<<<dim3(D1 / 128, (NN + 127) / 128), 256, SMEM_SZ>>>();
    alpha1_kernel<<<(NN + 7) / 8, 256>>>(as1, ad1);
    agg1_kernel<<<NN, 128>>>(b1);

    // Layer 2
    gemm2_kernel<<<(NN + 7) / 8, 256>>>(W2);
    alpha2_kernel<<<(NN + 255) / 256, 256>>>(as2, ad2);
    agg2_kernel<<<(NN + 3) / 4, 128>>>(b2, out);
}